// round 17
// baseline (speedup 1.0000x reference)
#include <cuda_runtime.h>
#include <math.h>

#define B_  32
#define S_  50
#define Q_  75
#define T_  128
#define F_  64
#define D_  256
#define KW  5
#define NS  (B_*S_)          // 1600 support samples
#define NQ  (B_*Q_)          // 2400 query samples
#define NTOT (NS+NQ)         // 4000
#define POOLB (NTOT/4)       // 1000 pool blocks
#define GRAMB F_             // 64 gram blocks
#define PROTB B_             // 32 proto blocks
#define QPB   16
#define DISTB (NQ/QPB)       // 150 dist blocks

// Scratch (device globals: allocation-free per harness rules)
__device__ float g_spooled[NS * F_];     // pooled support
__device__ float g_qfeat[NQ * F_];       // pooled queries
__device__ float g_G[F_ * F_];           // Gram G = W W^T
__device__ float g_h[B_ * KW * F_];      // h_k = G p_k
__device__ float g_c[B_ * KW];           // c_k = p_k . h_k
__device__ unsigned int g_cnt  = 0u;     // proto-done counter (self-resetting)
__device__ unsigned int g_done = 0u;     // dist-done counter  (self-resetting)

// ---------------------------------------------------------------------------
// K1: pool + gram in ONE launch — EXACT R12 body (measured 25.3us, DRAM 67%,
// regs 32). Do not touch.
// ---------------------------------------------------------------------------
__global__ void __launch_bounds__(256) poolgram_kernel(const float* __restrict__ sx,
                                                       const float* __restrict__ qx,
                                                       const float* __restrict__ Wm) {
    int tid = threadIdx.x;

    if (blockIdx.x < POOLB) {
        int lane    = tid & 31;
        int s_local = tid >> 6;          // 0..3
        int wis     = (tid >> 5) & 1;    // warp-in-sample
        int th      = lane >> 4;         // 0..1
        int f4      = lane & 15;         // 0..15

        int sn = blockIdx.x * 4 + s_local;
        const float4* src;
        float4* dstbase;
        if (sn < NS) {
            src     = reinterpret_cast<const float4*>(sx) + (size_t)sn * (T_ * F_ / 4);
            dstbase = reinterpret_cast<float4*>(g_spooled);
        } else {
            src     = reinterpret_cast<const float4*>(qx) + (size_t)(sn - NS) * (T_ * F_ / 4);
            dstbase = reinterpret_cast<float4*>(g_qfeat) - (size_t)NS * 16;
        }

        // t = wis*64 + th + 2*i, i = 0..31. Warp iteration reads 512B contig.
        const float4* p = src + (wis * 64 + th) * 16 + f4;
        float4 a0 = make_float4(0.f,0.f,0.f,0.f);
        float4 a1 = make_float4(0.f,0.f,0.f,0.f);
        #pragma unroll 4
        for (int i = 0; i < 32; i += 2) {
            float4 v0 = p[(2 * i)     * 16];
            float4 v1 = p[(2 * i + 2) * 16];
            a0.x += v0.x; a0.y += v0.y; a0.z += v0.z; a0.w += v0.w;
            a1.x += v1.x; a1.y += v1.y; a1.z += v1.z; a1.w += v1.w;
        }
        float4 a;
        a.x = a0.x + a1.x; a.y = a0.y + a1.y; a.z = a0.z + a1.z; a.w = a0.w + a1.w;
        a.x += __shfl_xor_sync(0xffffffffu, a.x, 16);
        a.y += __shfl_xor_sync(0xffffffffu, a.y, 16);
        a.z += __shfl_xor_sync(0xffffffffu, a.z, 16);
        a.w += __shfl_xor_sync(0xffffffffu, a.w, 16);

        __shared__ __align__(16) float4 part[4][2][16];
        if (th == 0) part[s_local][wis][f4] = a;
        __syncthreads();

        if (tid < 64) {
            int s = tid >> 4;
            int f = tid & 15;
            float4 u = part[s][0][f];
            float4 v = part[s][1][f];
            const float inv = 1.0f / (float)T_;
            float4 r;
            r.x = (u.x + v.x) * inv;
            r.y = (u.y + v.y) * inv;
            r.z = (u.z + v.z) * inv;
            r.w = (u.w + v.w) * inv;
            dstbase[(blockIdx.x * 4 + s) * 16 + f] = r;
        }
    } else {
        // ---- gram: block computes G row i; warp w owns j = w*8..w*8+7 ----
        int i    = blockIdx.x - POOLB;
        int warp = tid >> 5;
        int lane = tid & 31;

        float wi[8];
        #pragma unroll
        for (int u = 0; u < 8; u++)
            wi[u] = Wm[i * D_ + lane + 32 * u];

        float s[8];
        #pragma unroll
        for (int jj = 0; jj < 8; jj++) s[jj] = 0.f;

        #pragma unroll
        for (int u = 0; u < 8; u++) {
            #pragma unroll
            for (int jj = 0; jj < 8; jj++)
                s[jj] = fmaf(wi[u], Wm[(warp * 8 + jj) * D_ + lane + 32 * u], s[jj]);
        }

        #pragma unroll
        for (int jj = 0; jj < 8; jj++) {
            #pragma unroll
            for (int off = 16; off > 0; off >>= 1)
                s[jj] += __shfl_xor_sync(0xffffffffu, s[jj], off);
        }
        if (lane == 0) {
            #pragma unroll
            for (int jj = 0; jj < 8; jj++)
                g_G[i * F_ + warp * 8 + jj] = s[jj];
        }
    }
}

// ---------------------------------------------------------------------------
// Shared-memory union for the tail kernel. ONE kernel-scope __align__(16)
// object: R16's block-scoped __shared__ arrays got packed at 8-mod-16 offsets
// -> misaligned float4 (the R16 crash). Union guarantees Gs/Qs at offset 0 /
// 16384: both 16-aligned. Qs row stride 68 floats = 272 B = 17*16 (aligned).
// ---------------------------------------------------------------------------
struct ProtoSmem {
    float psh[KW][F_];
    float csh[KW][F_];
    int   ys[S_];
};
struct DistSmem {
    float Gs[F_ * F_];        // 16 KB, offset 0
    float Qs[QPB][68];        // offset 16384 (16-aligned)
    float hsh[2][KW][F_];
    float csh[2][KW];
};
union TailSmem {
    ProtoSmem p;
    DistSmem  d;
};

// ---------------------------------------------------------------------------
// K2: fused tail. grid = 32 proto + 150 dist = 182 blocks (< one wave, all
// resident at once -> dist's spin costs only proto's own ~2us latency, and
// steals NO residency from the pool kernel, which has already retired).
// ---------------------------------------------------------------------------
__global__ void __launch_bounds__(256) tail_kernel(const int* __restrict__ y,
                                                   float* __restrict__ out) {
    __shared__ __align__(16) TailSmem sm;
    int tid = threadIdx.x;

    if (blockIdx.x < PROTB) {
        // ================= proto =================
        int b = blockIdx.x;

        if (tid < S_) sm.p.ys[tid] = y[b * S_ + tid];
        __syncthreads();

        if (tid < F_) {
            int f = tid;
            float a0=0.f,a1=0.f,a2=0.f,a3=0.f,a4=0.f;
            int   c0=0,c1=0,c2=0,c3=0,c4=0;
            #pragma unroll 10
            for (int s = 0; s < S_; s++) {
                float v = g_spooled[(b * S_ + s) * F_ + f];
                int l = sm.p.ys[s];
                if (l == 0) { a0 += v; c0++; }
                if (l == 1) { a1 += v; c1++; }
                if (l == 2) { a2 += v; c2++; }
                if (l == 3) { a3 += v; c3++; }
                if (l == 4) { a4 += v; c4++; }
            }
            sm.p.psh[0][f] = c0 ? a0 / (float)c0 : 0.f;
            sm.p.psh[1][f] = c1 ? a1 / (float)c1 : 0.f;
            sm.p.psh[2][f] = c2 ? a2 / (float)c2 : 0.f;
            sm.p.psh[3][f] = c3 ? a3 / (float)c3 : 0.f;
            sm.p.psh[4][f] = c4 ? a4 / (float)c4 : 0.f;
        }
        __syncthreads();

        if (tid < F_) {
            int f = tid;
            float hk[KW];
            #pragma unroll
            for (int k = 0; k < KW; k++) hk[k] = 0.f;
            #pragma unroll 8
            for (int i = 0; i < F_; i++) {
                float gi = g_G[i * F_ + f];   // symmetric -> coalesced rows
                #pragma unroll
                for (int k = 0; k < KW; k++)
                    hk[k] = fmaf(gi, sm.p.psh[k][i], hk[k]);
            }
            #pragma unroll
            for (int k = 0; k < KW; k++) {
                g_h[(b * KW + k) * F_ + f] = hk[k];
                sm.p.csh[k][f] = sm.p.psh[k][f] * hk[k];
            }
        }
        __syncthreads();

        if (tid < 32) {
            #pragma unroll
            for (int k = 0; k < KW; k++) {
                float v = sm.p.csh[k][tid] + sm.p.csh[k][tid + 32];
                #pragma unroll
                for (int off = 16; off > 0; off >>= 1)
                    v += __shfl_xor_sync(0xffffffffu, v, off);
                if (tid == 0) g_c[b * KW + k] = v;
            }
        }
        // release
        __threadfence();
        __syncthreads();
        if (tid == 0) atomicAdd(&g_cnt, 1u);
        return;
    }

    // ================= dist =================
    {
        int q_local = tid >> 4;          // 0..15
        int jg      = tid & 15;          // columns jg*4..jg*4+3
        int dbid    = blockIdx.x - PROTB;
        int qbase   = dbid * QPB;        // 150*16 = 2400 exactly
        int bq      = qbase + q_local;
        int b0      = qbase / Q_;
        int b1      = (qbase + QPB - 1) / Q_;

        // G and query rows depend only on K1 -> stage BEFORE the spin
        {
            const float4* gsrc = reinterpret_cast<const float4*>(g_G);
            float4* gdst = reinterpret_cast<float4*>(sm.d.Gs);
            #pragma unroll
            for (int u = 0; u < 4; u++) gdst[tid + 256 * u] = gsrc[tid + 256 * u];
            int row = tid >> 4, c = tid & 15;
            float4 qv = reinterpret_cast<const float4*>(g_qfeat)[(qbase + row) * 16 + c];
            *reinterpret_cast<float4*>(&sm.d.Qs[row][c * 4]) = qv;
        }

        // acquire: wait for all proto blocks
        if (tid == 0) {
            while (*(volatile unsigned int*)&g_cnt < PROTB) __nanosleep(32);
        }
        __syncthreads();

        // stage h, c for the (up to) 2 episodes this block touches
        {
            float* hflat = &sm.d.hsh[0][0][0];
            for (int i = tid; i < 2 * KW * F_; i += 256) {
                int eb = i / (KW * F_);
                int be = eb ? b1 : b0;
                hflat[i] = g_h[be * KW * F_ + (i - eb * KW * F_)];
            }
            if (tid < 2 * KW) {
                int eb = tid / KW;
                sm.d.csh[eb][tid % KW] = g_c[(eb ? b1 : b0) * KW + tid % KW];
            }
        }
        __syncthreads();

        float e0 = 0.f, e1 = 0.f, e2 = 0.f, e3 = 0.f;
        #pragma unroll 16
        for (int k = 0; k < F_; k++) {
            float qk = sm.d.Qs[q_local][k];
            float4 g = *reinterpret_cast<const float4*>(&sm.d.Gs[k * F_ + jg * 4]);
            e0 = fmaf(g.x, qk, e0);
            e1 = fmaf(g.y, qk, e1);
            e2 = fmaf(g.z, qk, e2);
            e3 = fmaf(g.w, qk, e3);
        }
        float4 qj = *reinterpret_cast<const float4*>(&sm.d.Qs[q_local][jg * 4]);
        float a = e0 * qj.x + e1 * qj.y + e2 * qj.z + e3 * qj.w;

        int b  = bq / Q_;
        int eb = b - b0;
        float s[KW];
        #pragma unroll
        for (int k = 0; k < KW; k++) {
            float4 h4 = *reinterpret_cast<const float4*>(&sm.d.hsh[eb][k][jg * 4]);
            s[k] = qj.x * h4.x + qj.y * h4.y + qj.z * h4.z + qj.w * h4.w;
        }

        #pragma unroll
        for (int off = 8; off > 0; off >>= 1) {
            a += __shfl_xor_sync(0xffffffffu, a, off);
            #pragma unroll
            for (int k = 0; k < KW; k++)
                s[k] += __shfl_xor_sync(0xffffffffu, s[k], off);
        }

        if (jg == 0) {
            #pragma unroll
            for (int k = 0; k < KW; k++)
                out[bq * KW + k] = -sqrtf(fmaxf(a - 2.f * s[k] + sm.d.csh[eb][k], 0.f));
        }

        // self-reset counters for the next graph replay (last dist block)
        __syncthreads();
        if (tid == 0) {
            unsigned int dd = atomicAdd(&g_done, 1u);
            if (dd == DISTB - 1) {
                g_cnt  = 0u;
                g_done = 0u;
                __threadfence();
            }
        }
    }
}

// ---------------------------------------------------------------------------
// Inputs (metadata order): support_x f32, support_y i32, query_x f32, W f32, b f32
// Output: f32 [B*Q, KW] = [2400, 5]
// ---------------------------------------------------------------------------
extern "C" void kernel_launch(void* const* d_in, const int* in_sizes, int n_in,
                              void* d_out, int out_size) {
    const float* sx = (const float*)d_in[0];
    const int*   sy = (const int*)  d_in[1];
    const float* qx = (const float*)d_in[2];
    const float* Wm = (const float*)d_in[3];
    float* out = (float*)d_out;

    poolgram_kernel<<<POOLB + GRAMB,  256>>>(sx, qx, Wm);
    tail_kernel    <<<PROTB + DISTB,  256>>>(sy, out);
}